// round 2
// baseline (speedup 1.0000x reference)
#include <cuda_runtime.h>
#include <cuda_bf16.h>
#include <cstdint>

// Problem dims (fixed by dataset)
#define MDIM 8192
#define NDIM 4096
#define KDIM 4096

#define TILE_M 256
#define TILE_N 128
#define KC 64                                // K elements per chunk (128B rows)
#define CHUNKS_PER_PHASE (KDIM / KC)         // 64
#define NPHASE 3
#define NCHUNKS (NPHASE * CHUNKS_PER_PHASE)  // 192
#define STAGES 4

#define A_STAGE_BYTES (TILE_M * KC * 2)      // 32768
#define B_STAGE_BYTES (TILE_N * KC * 2)      // 16384
#define STAGE_BYTES (A_STAGE_BYTES + B_STAGE_BYTES)  // 49152
#define SMEM_BYTES (STAGES * STAGE_BYTES)    // 196608

// Split bf16 operand buffers (device globals; cudaMalloc forbidden)
__device__ __nv_bfloat16 g_Ah[(size_t)MDIM * KDIM];
__device__ __nv_bfloat16 g_Al[(size_t)MDIM * KDIM];
__device__ __nv_bfloat16 g_Bh[(size_t)NDIM * KDIM];  // [N][K] (transposed w_t)
__device__ __nv_bfloat16 g_Bl[(size_t)NDIM * KDIM];

// ---------------------------------------------------------------------------
// Helpers
// ---------------------------------------------------------------------------
__device__ __forceinline__ uint32_t smem_u32(const void* p) {
    uint32_t a;
    asm("{ .reg .u64 t; cvta.to.shared.u64 t, %1; cvt.u32.u64 %0, t; }"
        : "=r"(a) : "l"(p));
    return a;
}

__device__ __forceinline__ void cp_async16(uint32_t dst, const void* src) {
    asm volatile("cp.async.cg.shared.global [%0], [%1], 16;" :: "r"(dst), "l"(src));
}
__device__ __forceinline__ void cp_commit() {
    asm volatile("cp.async.commit_group;" ::: "memory");
}

__device__ __forceinline__ void ldsm_x4(uint32_t& r0, uint32_t& r1, uint32_t& r2, uint32_t& r3,
                                        uint32_t addr) {
    asm volatile("ldmatrix.sync.aligned.m8n8.x4.shared.b16 {%0,%1,%2,%3}, [%4];"
                 : "=r"(r0), "=r"(r1), "=r"(r2), "=r"(r3) : "r"(addr));
}

__device__ __forceinline__ void mma_16816(float& c0, float& c1, float& c2, float& c3,
                                          uint32_t a0, uint32_t a1, uint32_t a2, uint32_t a3,
                                          uint32_t b0, uint32_t b1) {
    asm volatile(
        "mma.sync.aligned.m16n8k16.row.col.f32.bf16.bf16.f32 "
        "{%0,%1,%2,%3}, {%4,%5,%6,%7}, {%8,%9}, {%0,%1,%2,%3};"
        : "+f"(c0), "+f"(c1), "+f"(c2), "+f"(c3)
        : "r"(a0), "r"(a1), "r"(a2), "r"(a3), "r"(b0), "r"(b1));
}

// ---------------------------------------------------------------------------
// Prep: fp32 -> bf16 hi/lo split; W also transposed to [N][K]
// ---------------------------------------------------------------------------
__global__ void split_x_kernel(const float* __restrict__ x) {
    size_t i = (size_t)blockIdx.x * blockDim.x + threadIdx.x;  // one float4 / thread
    float4 v = reinterpret_cast<const float4*>(x)[i];
    __nv_bfloat16 h0 = __float2bfloat16(v.x);
    __nv_bfloat16 h1 = __float2bfloat16(v.y);
    __nv_bfloat16 h2 = __float2bfloat16(v.z);
    __nv_bfloat16 h3 = __float2bfloat16(v.w);
    __nv_bfloat16 l0 = __float2bfloat16(v.x - __bfloat162float(h0));
    __nv_bfloat16 l1 = __float2bfloat16(v.y - __bfloat162float(h1));
    __nv_bfloat16 l2 = __float2bfloat16(v.z - __bfloat162float(h2));
    __nv_bfloat16 l3 = __float2bfloat16(v.w - __bfloat162float(h3));
    __nv_bfloat162* Ah2 = reinterpret_cast<__nv_bfloat162*>(g_Ah);
    __nv_bfloat162* Al2 = reinterpret_cast<__nv_bfloat162*>(g_Al);
    Ah2[i * 2 + 0] = __halves2bfloat162(h0, h1);
    Ah2[i * 2 + 1] = __halves2bfloat162(h2, h3);
    Al2[i * 2 + 0] = __halves2bfloat162(l0, l1);
    Al2[i * 2 + 1] = __halves2bfloat162(l2, l3);
}

// w_t is [K][N] fp32.  Produce g_Bh/g_Bl as [N][K] bf16.
__global__ void split_w_kernel(const float* __restrict__ wt) {
    __shared__ float t[32][33];
    int n0 = blockIdx.x * 32;
    int k0 = blockIdx.y * 32;
    int tx = threadIdx.x, ty = threadIdx.y;
#pragma unroll
    for (int j = 0; j < 4; j++)
        t[ty + j * 8][tx] = wt[(size_t)(k0 + ty + j * 8) * NDIM + n0 + tx];
    __syncthreads();
#pragma unroll
    for (int j = 0; j < 4; j++) {
        float v = t[tx][ty + j * 8];
        __nv_bfloat16 h = __float2bfloat16(v);
        __nv_bfloat16 l = __float2bfloat16(v - __bfloat162float(h));
        size_t o = (size_t)(n0 + ty + j * 8) * KDIM + k0 + tx;
        g_Bh[o] = h;
        g_Bl[o] = l;
    }
}

// ---------------------------------------------------------------------------
// bf16 mma.sync GEMM, 3-term split accumulation:
// out = Ah*Bh + Al*Bh + Ah*Bl  (all accumulated in fp32 registers)
// CTA 256x128, 16 warps (4x4), warp tile 64x32, KC=64, 4-stage cp.async.
// ---------------------------------------------------------------------------
__global__ void __launch_bounds__(512, 1)
gemm_kernel(float* __restrict__ out) {
    extern __shared__ char smem[];
    const uint32_t sbase = smem_u32(smem);

    const int tid = threadIdx.x;
    const int wid = tid >> 5;
    const int lid = tid & 31;
    const int wm = wid & 3;       // 0..3 -> M offset wm*64
    const int wn = wid >> 2;      // 0..3 -> N offset wn*32

    const int m0 = blockIdx.y * TILE_M;
    const int n0 = blockIdx.x * TILE_N;

    const __nv_bfloat16* Ap[NPHASE] = {g_Ah, g_Al, g_Ah};
    const __nv_bfloat16* Bp[NPHASE] = {g_Bh, g_Bh, g_Bl};

    // ---- load mapping: granule g -> (row = g>>3, c16 = g&7) ----
    // A: 2048 granules (4/thread), B: 1024 granules (2/thread)
    uint32_t a_sw[4], b_sw[2];
    size_t a_go[4], b_go[2];
#pragma unroll
    for (int j = 0; j < 4; j++) {
        int g = tid + j * 512;
        int r = g >> 3, c16 = g & 7;
        a_sw[j] = (uint32_t)(r * 128 + ((c16 * 16) ^ ((r & 7) << 4)));
        a_go[j] = (size_t)(m0 + r) * KDIM + c16 * 8;
    }
#pragma unroll
    for (int j = 0; j < 2; j++) {
        int g = tid + j * 512;
        int r = g >> 3, c16 = g & 7;
        b_sw[j] = (uint32_t)(A_STAGE_BYTES + r * 128 + ((c16 * 16) ^ ((r & 7) << 4)));
        b_go[j] = (size_t)(n0 + r) * KDIM + c16 * 8;
    }

    // ---- ldmatrix per-lane address components ----
    // A frag (m16k16): lanes 0-15 -> row (l&15), kbyte 0; lanes 16-31 -> row (l&15), kbyte 16
    const int a_row_l = lid & 15;
    const int a_kb_l = ((lid >> 4) & 1) * 16;
    // B frag pair (n16k16): row = (l&7) + (l>=16?8:0); kbyte = ((l>>3)&1)*16
    const int b_row_l = (lid & 7) + ((lid >> 4) & 1) * 8;
    const int b_kb_l = ((lid >> 3) & 1) * 16;

    uint32_t a_rowterm[4], a_xr[4];
#pragma unroll
    for (int mf = 0; mf < 4; mf++) {
        int r = wm * 64 + mf * 16 + a_row_l;
        a_rowterm[mf] = (uint32_t)(r * 128);
        a_xr[mf] = (uint32_t)((r & 7) << 4);
    }
    uint32_t b_rowterm[2], b_xr[2];
#pragma unroll
    for (int p = 0; p < 2; p++) {
        int r = wn * 32 + p * 16 + b_row_l;
        b_rowterm[p] = (uint32_t)(A_STAGE_BYTES + r * 128);
        b_xr[p] = (uint32_t)((r & 7) << 4);
    }

    float acc[4][4][4];  // [mf][nf][4]
#pragma unroll
    for (int i = 0; i < 4; i++)
#pragma unroll
        for (int j = 0; j < 4; j++)
#pragma unroll
            for (int q = 0; q < 4; q++) acc[i][j][q] = 0.f;

    auto issue_loads = [&](int cc) {
        const int p = cc >> 6;
        const size_t k0 = (size_t)((cc & 63) * KC);
        const uint32_t stage = sbase + (uint32_t)(cc & (STAGES - 1)) * STAGE_BYTES;
        const __nv_bfloat16* As = Ap[p];
        const __nv_bfloat16* Bs = Bp[p];
#pragma unroll
        for (int j = 0; j < 4; j++) cp_async16(stage + a_sw[j], As + a_go[j] + k0);
#pragma unroll
        for (int j = 0; j < 2; j++) cp_async16(stage + b_sw[j], Bs + b_go[j] + k0);
        cp_commit();
    };

    // prologue: 3 stages in flight
    issue_loads(0);
    issue_loads(1);
    issue_loads(2);

    for (int c = 0; c < NCHUNKS; c++) {
        asm volatile("cp.async.wait_group 2;" ::: "memory");
        __syncthreads();

        if (c + 3 < NCHUNKS) issue_loads(c + 3);

        const uint32_t stage = sbase + (uint32_t)(c & (STAGES - 1)) * STAGE_BYTES;
#pragma unroll
        for (int ks = 0; ks < 4; ks++) {
            uint32_t a[4][4];
            uint32_t b[2][4];
#pragma unroll
            for (int mf = 0; mf < 4; mf++) {
                uint32_t addr = stage + a_rowterm[mf] +
                                (((uint32_t)(a_kb_l + ks * 32)) ^ a_xr[mf]);
                ldsm_x4(a[mf][0], a[mf][1], a[mf][2], a[mf][3], addr);
            }
#pragma unroll
            for (int p = 0; p < 2; p++) {
                uint32_t addr = stage + b_rowterm[p] +
                                (((uint32_t)(b_kb_l + ks * 32)) ^ b_xr[p]);
                ldsm_x4(b[p][0], b[p][1], b[p][2], b[p][3], addr);
            }
#pragma unroll
            for (int mf = 0; mf < 4; mf++) {
#pragma unroll
                for (int nf = 0; nf < 4; nf++) {
                    mma_16816(acc[mf][nf][0], acc[mf][nf][1], acc[mf][nf][2], acc[mf][nf][3],
                              a[mf][0], a[mf][1], a[mf][2], a[mf][3],
                              b[nf >> 1][(nf & 1) * 2], b[nf >> 1][(nf & 1) * 2 + 1]);
                }
            }
        }
        __syncthreads();
    }

    // ---- epilogue: fp32 acc -> gmem ----
    const int row_base = m0 + wm * 64 + (lid >> 2);
    const int col_base = n0 + wn * 32 + (lid & 3) * 2;
#pragma unroll
    for (int mf = 0; mf < 4; mf++) {
#pragma unroll
        for (int nf = 0; nf < 4; nf++) {
            int r = row_base + mf * 16;
            int cl = col_base + nf * 8;
            float2* o0 = reinterpret_cast<float2*>(out + (size_t)r * NDIM + cl);
            float2* o1 = reinterpret_cast<float2*>(out + (size_t)(r + 8) * NDIM + cl);
            *o0 = make_float2(acc[mf][nf][0], acc[mf][nf][1]);
            *o1 = make_float2(acc[mf][nf][2], acc[mf][nf][3]);
        }
    }
}

// ---------------------------------------------------------------------------
// Launch
// ---------------------------------------------------------------------------
extern "C" void kernel_launch(void* const* d_in, const int* in_sizes, int n_in,
                              void* d_out, int out_size) {
    // Identify inputs by unique element counts: x = 8192*4096, w_t = 4096*4096
    const float* x = nullptr;
    const float* wt = nullptr;
    for (int i = 0; i < n_in; i++) {
        if (in_sizes[i] == 33554432) x = (const float*)d_in[i];
        else if (in_sizes[i] == 16777216) wt = (const float*)d_in[i];
    }

    cudaFuncSetAttribute(gemm_kernel, cudaFuncAttributeMaxDynamicSharedMemorySize, SMEM_BYTES);

    split_x_kernel<<<(MDIM * (size_t)KDIM) / 4 / 256, 256>>>(x);
    split_w_kernel<<<dim3(NDIM / 32, KDIM / 32), dim3(32, 8)>>>(wt);
    gemm_kernel<<<dim3(NDIM / TILE_N, MDIM / TILE_M), 512, SMEM_BYTES>>>((float*)d_out);
}

// round 3
// speedup vs baseline: 1.0723x; 1.0723x over previous
#include <cuda_runtime.h>
#include <cuda_bf16.h>
#include <cstdint>

// Problem dims (fixed by dataset)
#define MDIM 8192
#define NDIM 4096
#define KDIM 4096

#define TILE_M 256
#define TILE_N 128
#define KC 64                         // K per chunk
#define NCHUNKS (KDIM / KC)           // 64 (phases fused)
#define STAGES 2

// Stage layout: Ah(32K) Al(32K) Bh(16K) Bl(16K) = 96KB
#define AH_OFF 0
#define AL_OFF (TILE_M * KC * 2)              // 32768
#define BH_OFF (2 * TILE_M * KC * 2)          // 65536
#define BL_OFF (BH_OFF + TILE_N * KC * 2)     // 81920
#define STAGE_BYTES (BL_OFF + TILE_N * KC * 2) // 98304
#define SMEM_BYTES (STAGES * STAGE_BYTES)      // 196608

// Split bf16 operand buffers (device globals; cudaMalloc forbidden)
__device__ __nv_bfloat16 g_Ah[(size_t)MDIM * KDIM];
__device__ __nv_bfloat16 g_Al[(size_t)MDIM * KDIM];
__device__ __nv_bfloat16 g_Bh[(size_t)NDIM * KDIM];  // [N][K] (transposed w_t)
__device__ __nv_bfloat16 g_Bl[(size_t)NDIM * KDIM];

// ---------------------------------------------------------------------------
// Helpers
// ---------------------------------------------------------------------------
__device__ __forceinline__ uint32_t smem_u32(const void* p) {
    uint32_t a;
    asm("{ .reg .u64 t; cvta.to.shared.u64 t, %1; cvt.u32.u64 %0, t; }"
        : "=r"(a) : "l"(p));
    return a;
}

__device__ __forceinline__ void cp_async16(uint32_t dst, const void* src) {
    asm volatile("cp.async.cg.shared.global [%0], [%1], 16;" :: "r"(dst), "l"(src));
}
__device__ __forceinline__ void cp_commit() {
    asm volatile("cp.async.commit_group;" ::: "memory");
}

__device__ __forceinline__ void ldsm_x4(uint32_t& r0, uint32_t& r1, uint32_t& r2, uint32_t& r3,
                                        uint32_t addr) {
    asm volatile("ldmatrix.sync.aligned.m8n8.x4.shared.b16 {%0,%1,%2,%3}, [%4];"
                 : "=r"(r0), "=r"(r1), "=r"(r2), "=r"(r3) : "r"(addr));
}

__device__ __forceinline__ void mma_16816(float& c0, float& c1, float& c2, float& c3,
                                          uint32_t a0, uint32_t a1, uint32_t a2, uint32_t a3,
                                          uint32_t b0, uint32_t b1) {
    asm volatile(
        "mma.sync.aligned.m16n8k16.row.col.f32.bf16.bf16.f32 "
        "{%0,%1,%2,%3}, {%4,%5,%6,%7}, {%8,%9}, {%0,%1,%2,%3};"
        : "+f"(c0), "+f"(c1), "+f"(c2), "+f"(c3)
        : "r"(a0), "r"(a1), "r"(a2), "r"(a3), "r"(b0), "r"(b1));
}

// ---------------------------------------------------------------------------
// Prep: fp32 -> bf16 hi/lo split; W also transposed to [N][K]
// ---------------------------------------------------------------------------
__global__ void split_x_kernel(const float* __restrict__ x) {
    size_t i = (size_t)blockIdx.x * blockDim.x + threadIdx.x;  // one float4 / thread
    float4 v = reinterpret_cast<const float4*>(x)[i];
    __nv_bfloat16 h0 = __float2bfloat16(v.x);
    __nv_bfloat16 h1 = __float2bfloat16(v.y);
    __nv_bfloat16 h2 = __float2bfloat16(v.z);
    __nv_bfloat16 h3 = __float2bfloat16(v.w);
    __nv_bfloat16 l0 = __float2bfloat16(v.x - __bfloat162float(h0));
    __nv_bfloat16 l1 = __float2bfloat16(v.y - __bfloat162float(h1));
    __nv_bfloat16 l2 = __float2bfloat16(v.z - __bfloat162float(h2));
    __nv_bfloat16 l3 = __float2bfloat16(v.w - __bfloat162float(h3));
    __nv_bfloat162* Ah2 = reinterpret_cast<__nv_bfloat162*>(g_Ah);
    __nv_bfloat162* Al2 = reinterpret_cast<__nv_bfloat162*>(g_Al);
    Ah2[i * 2 + 0] = __halves2bfloat162(h0, h1);
    Ah2[i * 2 + 1] = __halves2bfloat162(h2, h3);
    Al2[i * 2 + 0] = __halves2bfloat162(l0, l1);
    Al2[i * 2 + 1] = __halves2bfloat162(l2, l3);
}

// w_t is [K][N] fp32.  Produce g_Bh/g_Bl as [N][K] bf16.
__global__ void split_w_kernel(const float* __restrict__ wt) {
    __shared__ float t[32][33];
    int n0 = blockIdx.x * 32;
    int k0 = blockIdx.y * 32;
    int tx = threadIdx.x, ty = threadIdx.y;
#pragma unroll
    for (int j = 0; j < 4; j++)
        t[ty + j * 8][tx] = wt[(size_t)(k0 + ty + j * 8) * NDIM + n0 + tx];
    __syncthreads();
#pragma unroll
    for (int j = 0; j < 4; j++) {
        float v = t[tx][ty + j * 8];
        __nv_bfloat16 h = __float2bfloat16(v);
        __nv_bfloat16 l = __float2bfloat16(v - __bfloat162float(h));
        size_t o = (size_t)(n0 + ty + j * 8) * KDIM + k0 + tx;
        g_Bh[o] = h;
        g_Bl[o] = l;
    }
}

// ---------------------------------------------------------------------------
// Fused 3-term bf16 GEMM: out = Ah*Bh + Al*Bh + Ah*Bl (fp32 accum).
// Per K-chunk all four tiles (Ah, Al, Bh, Bl) are loaded once; 3 MMA sets run
// on the shared fragments. CTA 256x128, 16 warps (4x4), warp tile 64x32.
// ---------------------------------------------------------------------------
__global__ void __launch_bounds__(512, 1)
gemm_kernel(float* __restrict__ out) {
    extern __shared__ char smem[];
    const uint32_t sbase = smem_u32(smem);

    const int tid = threadIdx.x;
    const int wid = tid >> 5;
    const int lid = tid & 31;
    const int wm = wid & 3;       // M offset wm*64
    const int wn = wid >> 2;      // N offset wn*32

    const int m0 = blockIdx.y * TILE_M;
    const int n0 = blockIdx.x * TILE_N;

    // ---- load mapping: granule g -> (row = g>>3, c16 = g&7), 128B rows ----
    uint32_t a_sw[4], b_sw[2];
    size_t a_go[4], b_go[2];
#pragma unroll
    for (int j = 0; j < 4; j++) {
        int g = tid + j * 512;
        int r = g >> 3, c16 = g & 7;
        a_sw[j] = (uint32_t)(r * 128 + ((c16 * 16) ^ ((r & 7) << 4)));
        a_go[j] = (size_t)(m0 + r) * KDIM + c16 * 8;
    }
#pragma unroll
    for (int j = 0; j < 2; j++) {
        int g = tid + j * 512;
        int r = g >> 3, c16 = g & 7;
        b_sw[j] = (uint32_t)(r * 128 + ((c16 * 16) ^ ((r & 7) << 4)));
        b_go[j] = (size_t)(n0 + r) * KDIM + c16 * 8;
    }

    // ---- ldmatrix per-lane address components ----
    const int a_row_l = lid & 15;
    const int a_kb_l = ((lid >> 4) & 1) * 16;
    const int b_row_l = (lid & 7) + ((lid >> 4) & 1) * 8;
    const int b_kb_l = ((lid >> 3) & 1) * 16;

    uint32_t a_rowterm[4], a_xr[4];
#pragma unroll
    for (int mf = 0; mf < 4; mf++) {
        int r = wm * 64 + mf * 16 + a_row_l;
        a_rowterm[mf] = (uint32_t)(r * 128);
        a_xr[mf] = (uint32_t)((r & 7) << 4);
    }
    uint32_t b_rowterm[2], b_xr[2];
#pragma unroll
    for (int p = 0; p < 2; p++) {
        int r = wn * 32 + p * 16 + b_row_l;
        b_rowterm[p] = (uint32_t)(r * 128);
        b_xr[p] = (uint32_t)((r & 7) << 4);
    }

    float acc[4][4][4];  // [mf][nf][4]
#pragma unroll
    for (int i = 0; i < 4; i++)
#pragma unroll
        for (int j = 0; j < 4; j++)
#pragma unroll
            for (int q = 0; q < 4; q++) acc[i][j][q] = 0.f;

    auto issue_loads = [&](int cc) {
        const size_t k0 = (size_t)(cc * KC);
        const uint32_t stage = sbase + (uint32_t)(cc & (STAGES - 1)) * STAGE_BYTES;
#pragma unroll
        for (int j = 0; j < 4; j++) {
            cp_async16(stage + AH_OFF + a_sw[j], g_Ah + a_go[j] + k0);
            cp_async16(stage + AL_OFF + a_sw[j], g_Al + a_go[j] + k0);
        }
#pragma unroll
        for (int j = 0; j < 2; j++) {
            cp_async16(stage + BH_OFF + b_sw[j], g_Bh + b_go[j] + k0);
            cp_async16(stage + BL_OFF + b_sw[j], g_Bl + b_go[j] + k0);
        }
        cp_commit();
    };

    // prologue: both stages in flight
    issue_loads(0);
    issue_loads(1);

    for (int c = 0; c < NCHUNKS; c++) {
        if (c == NCHUNKS - 1)
            asm volatile("cp.async.wait_group 0;" ::: "memory");
        else
            asm volatile("cp.async.wait_group 1;" ::: "memory");
        __syncthreads();

        const uint32_t stage = sbase + (uint32_t)(c & (STAGES - 1)) * STAGE_BYTES;

#pragma unroll
        for (int ks = 0; ks < 4; ks++) {
            const uint32_t a_kx = (uint32_t)(a_kb_l + ks * 32);
            const uint32_t b_kx = (uint32_t)(b_kb_l + ks * 32);

            uint32_t ah[4][4], al[4][4];
            uint32_t b[2][4];

            // --- Ah, Bh fragments; hh MMAs ---
#pragma unroll
            for (int mf = 0; mf < 4; mf++)
                ldsm_x4(ah[mf][0], ah[mf][1], ah[mf][2], ah[mf][3],
                        stage + AH_OFF + a_rowterm[mf] + (a_kx ^ a_xr[mf]));
#pragma unroll
            for (int p = 0; p < 2; p++)
                ldsm_x4(b[p][0], b[p][1], b[p][2], b[p][3],
                        stage + BH_OFF + b_rowterm[p] + (b_kx ^ b_xr[p]));
#pragma unroll
            for (int mf = 0; mf < 4; mf++)
#pragma unroll
                for (int nf = 0; nf < 4; nf++)
                    mma_16816(acc[mf][nf][0], acc[mf][nf][1], acc[mf][nf][2], acc[mf][nf][3],
                              ah[mf][0], ah[mf][1], ah[mf][2], ah[mf][3],
                              b[nf >> 1][(nf & 1) * 2], b[nf >> 1][(nf & 1) * 2 + 1]);

            // --- Al fragments; lh MMAs (reuse Bh fragments) ---
#pragma unroll
            for (int mf = 0; mf < 4; mf++)
                ldsm_x4(al[mf][0], al[mf][1], al[mf][2], al[mf][3],
                        stage + AL_OFF + a_rowterm[mf] + (a_kx ^ a_xr[mf]));
#pragma unroll
            for (int mf = 0; mf < 4; mf++)
#pragma unroll
                for (int nf = 0; nf < 4; nf++)
                    mma_16816(acc[mf][nf][0], acc[mf][nf][1], acc[mf][nf][2], acc[mf][nf][3],
                              al[mf][0], al[mf][1], al[mf][2], al[mf][3],
                              b[nf >> 1][(nf & 1) * 2], b[nf >> 1][(nf & 1) * 2 + 1]);

            // --- Bl fragments (overwrite b regs); hl MMAs (reuse Ah) ---
#pragma unroll
            for (int p = 0; p < 2; p++)
                ldsm_x4(b[p][0], b[p][1], b[p][2], b[p][3],
                        stage + BL_OFF + b_rowterm[p] + (b_kx ^ b_xr[p]));
#pragma unroll
            for (int mf = 0; mf < 4; mf++)
#pragma unroll
                for (int nf = 0; nf < 4; nf++)
                    mma_16816(acc[mf][nf][0], acc[mf][nf][1], acc[mf][nf][2], acc[mf][nf][3],
                              ah[mf][0], ah[mf][1], ah[mf][2], ah[mf][3],
                              b[nf >> 1][(nf & 1) * 2], b[nf >> 1][(nf & 1) * 2 + 1]);
        }

        __syncthreads();
        if (c + 2 < NCHUNKS) issue_loads(c + 2);
    }

    // ---- epilogue: fp32 acc -> gmem ----
    const int row_base = m0 + wm * 64 + (lid >> 2);
    const int col_base = n0 + wn * 32 + (lid & 3) * 2;
#pragma unroll
    for (int mf = 0; mf < 4; mf++) {
#pragma unroll
        for (int nf = 0; nf < 4; nf++) {
            int r = row_base + mf * 16;
            int cl = col_base + nf * 8;
            float2* o0 = reinterpret_cast<float2*>(out + (size_t)r * NDIM + cl);
            float2* o1 = reinterpret_cast<float2*>(out + (size_t)(r + 8) * NDIM + cl);
            *o0 = make_float2(acc[mf][nf][0], acc[mf][nf][1]);
            *o1 = make_float2(acc[mf][nf][2], acc[mf][nf][3]);
        }
    }
}

// ---------------------------------------------------------------------------
// Launch
// ---------------------------------------------------------------------------
extern "C" void kernel_launch(void* const* d_in, const int* in_sizes, int n_in,
                              void* d_out, int out_size) {
    // Identify inputs by unique element counts: x = 8192*4096, w_t = 4096*4096
    const float* x = nullptr;
    const float* wt = nullptr;
    for (int i = 0; i < n_in; i++) {
        if (in_sizes[i] == 33554432) x = (const float*)d_in[i];
        else if (in_sizes[i] == 16777216) wt = (const float*)d_in[i];
    }

    cudaFuncSetAttribute(gemm_kernel, cudaFuncAttributeMaxDynamicSharedMemorySize, SMEM_BYTES);

    split_x_kernel<<<(MDIM * (size_t)KDIM) / 4 / 256, 256>>>(x);
    split_w_kernel<<<dim3(NDIM / 32, KDIM / 32), dim3(32, 8)>>>(wt);
    gemm_kernel<<<dim3(NDIM / TILE_N, MDIM / TILE_M), 512, SMEM_BYTES>>>((float*)d_out);
}

// round 4
// speedup vs baseline: 2.8424x; 2.6508x over previous
#include <cuda_runtime.h>
#include <cuda_fp16.h>
#include <cstdint>

// Problem dims (fixed by dataset)
#define MDIM 8192
#define NDIM 4096
#define KDIM 4096

#define TILE_M 256
#define TILE_N 128
#define KC 64                         // K per chunk
#define NCHUNKS (KDIM / KC)           // 64
#define STAGES 4

#define A_STAGE_BYTES (TILE_M * KC * 2)               // 32768
#define B_STAGE_BYTES (TILE_N * KC * 2)               // 16384
#define STAGE_BYTES (A_STAGE_BYTES + B_STAGE_BYTES)   // 49152
#define SMEM_BYTES (STAGES * STAGE_BYTES)             // 196608

// fp16 operand buffers (device globals; cudaMalloc forbidden)
__device__ __half g_A[(size_t)MDIM * KDIM];
__device__ __half g_B[(size_t)NDIM * KDIM];  // [N][K] (transposed w_t)

// ---------------------------------------------------------------------------
// Helpers
// ---------------------------------------------------------------------------
__device__ __forceinline__ uint32_t smem_u32(const void* p) {
    uint32_t a;
    asm("{ .reg .u64 t; cvta.to.shared.u64 t, %1; cvt.u32.u64 %0, t; }"
        : "=r"(a) : "l"(p));
    return a;
}

__device__ __forceinline__ void cp_async16(uint32_t dst, const void* src) {
    asm volatile("cp.async.cg.shared.global [%0], [%1], 16;" :: "r"(dst), "l"(src));
}
__device__ __forceinline__ void cp_commit() {
    asm volatile("cp.async.commit_group;" ::: "memory");
}

__device__ __forceinline__ void ldsm_x4(uint32_t& r0, uint32_t& r1, uint32_t& r2, uint32_t& r3,
                                        uint32_t addr) {
    asm volatile("ldmatrix.sync.aligned.m8n8.x4.shared.b16 {%0,%1,%2,%3}, [%4];"
                 : "=r"(r0), "=r"(r1), "=r"(r2), "=r"(r3) : "r"(addr));
}

__device__ __forceinline__ void mma_16816(float& c0, float& c1, float& c2, float& c3,
                                          uint32_t a0, uint32_t a1, uint32_t a2, uint32_t a3,
                                          uint32_t b0, uint32_t b1) {
    asm volatile(
        "mma.sync.aligned.m16n8k16.row.col.f32.f16.f16.f32 "
        "{%0,%1,%2,%3}, {%4,%5,%6,%7}, {%8,%9}, {%0,%1,%2,%3};"
        : "+f"(c0), "+f"(c1), "+f"(c2), "+f"(c3)
        : "r"(a0), "r"(a1), "r"(a2), "r"(a3), "r"(b0), "r"(b1));
}

// ---------------------------------------------------------------------------
// Prep: fp32 -> fp16; W also transposed to [N][K]
// ---------------------------------------------------------------------------
__global__ void conv_x_kernel(const float* __restrict__ x) {
    size_t i = (size_t)blockIdx.x * blockDim.x + threadIdx.x;  // one float4 / thread
    float4 v = reinterpret_cast<const float4*>(x)[i];
    __half2* A2 = reinterpret_cast<__half2*>(g_A);
    A2[i * 2 + 0] = __floats2half2_rn(v.x, v.y);
    A2[i * 2 + 1] = __floats2half2_rn(v.z, v.w);
}

// w_t is [K][N] fp32.  Produce g_B as [N][K] fp16.
__global__ void conv_w_kernel(const float* __restrict__ wt) {
    __shared__ float t[32][33];
    int n0 = blockIdx.x * 32;
    int k0 = blockIdx.y * 32;
    int tx = threadIdx.x, ty = threadIdx.y;
#pragma unroll
    for (int j = 0; j < 4; j++)
        t[ty + j * 8][tx] = wt[(size_t)(k0 + ty + j * 8) * NDIM + n0 + tx];
    __syncthreads();
#pragma unroll
    for (int j = 0; j < 4; j++) {
        float v = t[tx][ty + j * 8];
        g_B[(size_t)(n0 + ty + j * 8) * KDIM + k0 + tx] = __float2half_rn(v);
    }
}

// ---------------------------------------------------------------------------
// Single fp16 GEMM, fp32 accumulate.
// CTA 256x128, 16 warps (4x4), warp tile 64x32, KC=64, 4-stage cp.async.
// ---------------------------------------------------------------------------
__global__ void __launch_bounds__(512, 1)
gemm_kernel(float* __restrict__ out) {
    extern __shared__ char smem[];
    const uint32_t sbase = smem_u32(smem);

    const int tid = threadIdx.x;
    const int wid = tid >> 5;
    const int lid = tid & 31;
    const int wm = wid & 3;       // M offset wm*64
    const int wn = wid >> 2;      // N offset wn*32

    const int m0 = blockIdx.y * TILE_M;
    const int n0 = blockIdx.x * TILE_N;

    // ---- load mapping: granule g -> (row = g>>3, c16 = g&7), 128B rows ----
    uint32_t a_sw[4], b_sw[2];
    size_t a_go[4], b_go[2];
#pragma unroll
    for (int j = 0; j < 4; j++) {
        int g = tid + j * 512;
        int r = g >> 3, c16 = g & 7;
        a_sw[j] = (uint32_t)(r * 128 + ((c16 * 16) ^ ((r & 7) << 4)));
        a_go[j] = (size_t)(m0 + r) * KDIM + c16 * 8;
    }
#pragma unroll
    for (int j = 0; j < 2; j++) {
        int g = tid + j * 512;
        int r = g >> 3, c16 = g & 7;
        b_sw[j] = (uint32_t)(A_STAGE_BYTES + r * 128 + ((c16 * 16) ^ ((r & 7) << 4)));
        b_go[j] = (size_t)(n0 + r) * KDIM + c16 * 8;
    }

    // ---- ldmatrix per-lane address components ----
    const int a_row_l = lid & 15;
    const int a_kb_l = ((lid >> 4) & 1) * 16;
    const int b_row_l = (lid & 7) + ((lid >> 4) & 1) * 8;
    const int b_kb_l = ((lid >> 3) & 1) * 16;

    uint32_t a_rowterm[4], a_xr[4];
#pragma unroll
    for (int mf = 0; mf < 4; mf++) {
        int r = wm * 64 + mf * 16 + a_row_l;
        a_rowterm[mf] = (uint32_t)(r * 128);
        a_xr[mf] = (uint32_t)((r & 7) << 4);
    }
    uint32_t b_rowterm[2], b_xr[2];
#pragma unroll
    for (int p = 0; p < 2; p++) {
        int r = wn * 32 + p * 16 + b_row_l;
        b_rowterm[p] = (uint32_t)(A_STAGE_BYTES + r * 128);
        b_xr[p] = (uint32_t)((r & 7) << 4);
    }

    float acc[4][4][4];  // [mf][nf][4]
#pragma unroll
    for (int i = 0; i < 4; i++)
#pragma unroll
        for (int j = 0; j < 4; j++)
#pragma unroll
            for (int q = 0; q < 4; q++) acc[i][j][q] = 0.f;

    auto issue_loads = [&](int cc) {
        const size_t k0 = (size_t)(cc * KC);
        const uint32_t stage = sbase + (uint32_t)(cc & (STAGES - 1)) * STAGE_BYTES;
#pragma unroll
        for (int j = 0; j < 4; j++) cp_async16(stage + a_sw[j], g_A + a_go[j] + k0);
#pragma unroll
        for (int j = 0; j < 2; j++) cp_async16(stage + b_sw[j], g_B + b_go[j] + k0);
        cp_commit();
    };

    // prologue: 3 stages in flight
    issue_loads(0);
    issue_loads(1);
    issue_loads(2);

    for (int c = 0; c < NCHUNKS; c++) {
        asm volatile("cp.async.wait_group 2;" ::: "memory");
        __syncthreads();

        // stage (c+3)&3 == (c-1)&3 was fully consumed before the sync above
        if (c + 3 < NCHUNKS) issue_loads(c + 3);

        const uint32_t stage = sbase + (uint32_t)(c & (STAGES - 1)) * STAGE_BYTES;
#pragma unroll
        for (int ks = 0; ks < 4; ks++) {
            const uint32_t a_kx = (uint32_t)(a_kb_l + ks * 32);
            const uint32_t b_kx = (uint32_t)(b_kb_l + ks * 32);

            uint32_t a[4][4];
            uint32_t b[2][4];
#pragma unroll
            for (int mf = 0; mf < 4; mf++)
                ldsm_x4(a[mf][0], a[mf][1], a[mf][2], a[mf][3],
                        stage + a_rowterm[mf] + (a_kx ^ a_xr[mf]));
#pragma unroll
            for (int p = 0; p < 2; p++)
                ldsm_x4(b[p][0], b[p][1], b[p][2], b[p][3],
                        stage + b_rowterm[p] + (b_kx ^ b_xr[p]));
#pragma unroll
            for (int mf = 0; mf < 4; mf++)
#pragma unroll
                for (int nf = 0; nf < 4; nf++)
                    mma_16816(acc[mf][nf][0], acc[mf][nf][1], acc[mf][nf][2], acc[mf][nf][3],
                              a[mf][0], a[mf][1], a[mf][2], a[mf][3],
                              b[nf >> 1][(nf & 1) * 2], b[nf >> 1][(nf & 1) * 2 + 1]);
        }
        __syncthreads();
    }

    // ---- epilogue: fp32 acc -> gmem ----
    const int row_base = m0 + wm * 64 + (lid >> 2);
    const int col_base = n0 + wn * 32 + (lid & 3) * 2;
#pragma unroll
    for (int mf = 0; mf < 4; mf++) {
#pragma unroll
        for (int nf = 0; nf < 4; nf++) {
            int r = row_base + mf * 16;
            int cl = col_base + nf * 8;
            float2* o0 = reinterpret_cast<float2*>(out + (size_t)r * NDIM + cl);
            float2* o1 = reinterpret_cast<float2*>(out + (size_t)(r + 8) * NDIM + cl);
            *o0 = make_float2(acc[mf][nf][0], acc[mf][nf][1]);
            *o1 = make_float2(acc[mf][nf][2], acc[mf][nf][3]);
        }
    }
}

// ---------------------------------------------------------------------------
// Launch
// ---------------------------------------------------------------------------
extern "C" void kernel_launch(void* const* d_in, const int* in_sizes, int n_in,
                              void* d_out, int out_size) {
    // Identify inputs by unique element counts: x = 8192*4096, w_t = 4096*4096
    const float* x = nullptr;
    const float* wt = nullptr;
    for (int i = 0; i < n_in; i++) {
        if (in_sizes[i] == 33554432) x = (const float*)d_in[i];
        else if (in_sizes[i] == 16777216) wt = (const float*)d_in[i];
    }

    cudaFuncSetAttribute(gemm_kernel, cudaFuncAttributeMaxDynamicSharedMemorySize, SMEM_BYTES);

    conv_x_kernel<<<(MDIM * (size_t)KDIM) / 4 / 256, 256>>>(x);
    conv_w_kernel<<<dim3(NDIM / 32, KDIM / 32), dim3(32, 8)>>>(wt);
    gemm_kernel<<<dim3(NDIM / TILE_N, MDIM / TILE_M), 512, SMEM_BYTES>>>((float*)d_out);
}